// round 14
// baseline (speedup 1.0000x reference)
#include <cuda_runtime.h>
#include <cstdint>

#define BSZ 8
#define NPT 1024
#define KNN 20
#define NEG 0.2f
#define EPSB 1e-5f
#define NPTS_TOT (BSZ*NPT)
#define FLTMAX 3.402823466e38f

// ------------------------- scratch (device globals; no allocs) -------------
__device__ float  g_X0 [BSZ*NPT*3];
__device__ float  g_XX [BSZ*NPT];
__device__ float  g_PD [BSZ*NPT*NPT];        // 32 MB pairwise scores
__device__ int    g_IDX[BSZ*NPT*KNN];
__device__ float  g_YMX[BSZ*NPT*256];
__device__ float  g_YMN[BSZ*NPT*256];
__device__ float  g_CAT[BSZ*NPT*512];        // x1|x2|x3|x4 per point row
__device__ float  g_Y5 [BSZ*NPT*1024];       // 32 MB conv5 output
__device__ float  g_WC [512*128];            // L4 combined [W1; W2-W1]
__device__ float  g_PQ [BSZ*NPT*512];        // L4 [P | Q] per point (16 MB)
__device__ double g_SUM[1024];               // zero-init at load; bnfin re-zeroes
__device__ double g_SQS[1024];
__device__ float  g_M  [1024];
__device__ float  g_RS [1024];
__device__ float  g_FEAT[BSZ*2048];
__device__ float  g_H1 [BSZ*512];
__device__ float  g_H2 [BSZ*256];

// ------------------------- small utility kernels ---------------------------
__global__ void transpose_x_kernel(const float* __restrict__ x, float* __restrict__ X0) {
    int i = blockIdx.x * blockDim.x + threadIdx.x;
    if (i < BSZ*NPT*3) {
        int b = i / (NPT*3); int rest = i % (NPT*3);
        int n = rest / 3, c = rest % 3;
        X0[i] = x[((size_t)b*3 + c)*NPT + n];
    }
}

// xx[n] = sum_c x[n,c]^2  — square rounded, then ascending adds (NO fma)
__global__ void rownorm_kernel(const float* __restrict__ X, int ld, int Cin,
                               float* __restrict__ xx) {
    int pt = blockIdx.x * blockDim.x + threadIdx.x;
    if (pt < NPTS_TOT) {
        const float* r = X + (size_t)pt * ld;
        float s = 0.f;
        for (int c = 0; c < Cin; c++) {
            float v = r[c];
            s = __fadd_rn(s, __fmul_rn(v, v));
        }
        xx[pt] = s;
    }
}

// L4 combined weights: WC[o] = W1[o]; WC[Cout+o] = W2[o]-W1[o]
__global__ void wcomb_kernel(const float* __restrict__ W, int Cin, int Cout,
                             float* __restrict__ WC) {
    int i = blockIdx.x * blockDim.x + threadIdx.x;
    if (i < 2*Cout*Cin) {
        int o = i / Cin, c = i % Cin;
        if (o < Cout) WC[i] = W[(size_t)o*(2*Cin) + c];
        else {
            int oo = o - Cout;
            WC[i] = __fsub_rn(W[(size_t)oo*(2*Cin) + Cin + c],
                              W[(size_t)oo*(2*Cin) + c]);
        }
    }
}

// From fp64 sums: m, rs — then RE-ZEROES the stats slots for the next phase.
__global__ void bnfin_kernel(double* __restrict__ sum, double* __restrict__ sqs,
                             double cnt, int C,
                             float* __restrict__ M, float* __restrict__ RS) {
    int o = blockIdx.x * blockDim.x + threadIdx.x;
    if (o < C) {
        double mu = sum[o] / cnt;
        float m = (float)mu;
        double vd = sqs[o]/cnt - 2.0*(double)m*mu + (double)m*(double)m;
        float v = (float)vd;
        M[o]  = m;
        RS[o] = rsqrtf(__fadd_rn(v, EPSB));
        sum[o] = 0.0;
        sqs[o] = 0.0;
    }
}

// ------------------------- tiled fp32 GEMM (128x64, 256 thr, 8x4, dbuf) ----
// C[b,i,j] = sum_c X[b,i,c]*W[j,c], ascending-K single-accumulator fma chain.
__global__ void gemm_xw_kernel(const float* __restrict__ X, int ldx, int Cin,
                               const float* __restrict__ W,
                               float* __restrict__ out, int ldo) {
    int b  = blockIdx.z;
    int i0 = blockIdx.x * 128;
    int j0 = blockIdx.y * 64;
    __shared__ float As[2][16][132];
    __shared__ float Bs[2][16][68];
    int tid = threadIdx.x, tx = tid % 16, ty = tid / 16;
    float acc[8][4] = {};
    const float* Xb = X + (size_t)b * NPT * ldx;
    int T = (Cin + 15) >> 4;
    #pragma unroll
    for (int n = 0; n < 8; n++) {
        int l = tid + 256*n; int r = l >> 4, c = l & 15;
        As[0][c][r] = (c < Cin) ? Xb[(size_t)(i0 + r)*ldx + c] : 0.f;
    }
    #pragma unroll
    for (int n = 0; n < 4; n++) {
        int l = tid + 256*n; int r = l >> 4, c = l & 15;
        Bs[0][c][r] = (c < Cin) ? W[(size_t)(j0 + r)*Cin + c] : 0.f;
    }
    __syncthreads();
    for (int t = 0; t < T; t++) {
        int cur = t & 1, nxt = cur ^ 1;
        float pa[8], pb[4];
        if (t + 1 < T) {
            int k0n = (t + 1) << 4;
            #pragma unroll
            for (int n = 0; n < 8; n++) {
                int l = tid + 256*n; int r = l >> 4, c = l & 15; int kk = k0n + c;
                pa[n] = (kk < Cin) ? Xb[(size_t)(i0 + r)*ldx + kk] : 0.f;
            }
            #pragma unroll
            for (int n = 0; n < 4; n++) {
                int l = tid + 256*n; int r = l >> 4, c = l & 15; int kk = k0n + c;
                pb[n] = (kk < Cin) ? W[(size_t)(j0 + r)*Cin + kk] : 0.f;
            }
        }
        #pragma unroll
        for (int kk = 0; kk < 16; kk++) {
            float4 a0 = *(const float4*)&As[cur][kk][ty*8];
            float4 a1 = *(const float4*)&As[cur][kk][ty*8 + 4];
            float4 bq = *(const float4*)&Bs[cur][kk][tx*4];
            float a[8]  = {a0.x,a0.y,a0.z,a0.w,a1.x,a1.y,a1.z,a1.w};
            float bv[4] = {bq.x, bq.y, bq.z, bq.w};
            #pragma unroll
            for (int i = 0; i < 8; i++)
                #pragma unroll
                for (int j = 0; j < 4; j++)
                    acc[i][j] = __fmaf_rn(a[i], bv[j], acc[i][j]);
        }
        if (t + 1 < T) {
            #pragma unroll
            for (int n = 0; n < 8; n++) {
                int l = tid + 256*n; int r = l >> 4, c = l & 15;
                As[nxt][c][r] = pa[n];
            }
            #pragma unroll
            for (int n = 0; n < 4; n++) {
                int l = tid + 256*n; int r = l >> 4, c = l & 15;
                Bs[nxt][c][r] = pb[n];
            }
        }
        __syncthreads();
    }
    float* outb = out + (size_t)b * NPT * ldo;
    #pragma unroll
    for (int i = 0; i < 8; i++) {
        float4 v = make_float4(acc[i][0], acc[i][1], acc[i][2], acc[i][3]);
        *(float4*)&outb[(size_t)(i0 + ty*8 + i)*ldo + (j0 + tx*4)] = v;
    }
}

// pd[b,i,j] = (-xx[j] - (-2*dot_ij)) - xx[i], dot via ascending fma (exact fp32)
// R10 configuration: 128x64 tile, 8x4 micro, double-buffered.
__global__ void gram_kernel(const float* __restrict__ X, int ldx, int Cin,
                            const float* __restrict__ xx, float* __restrict__ S) {
    int b  = blockIdx.z;
    int i0 = blockIdx.x * 128;
    int j0 = blockIdx.y * 64;
    __shared__ float As[2][16][132];
    __shared__ float Bs[2][16][68];
    int tid = threadIdx.x, tx = tid % 16, ty = tid / 16;
    float acc[8][4] = {};
    const float* Xb = X + (size_t)b * NPT * ldx;
    int T = (Cin + 15) >> 4;
    #pragma unroll
    for (int n = 0; n < 8; n++) {
        int l = tid + 256*n; int r = l >> 4, c = l & 15;
        As[0][c][r] = (c < Cin) ? Xb[(size_t)(i0 + r)*ldx + c] : 0.f;
    }
    #pragma unroll
    for (int n = 0; n < 4; n++) {
        int l = tid + 256*n; int r = l >> 4, c = l & 15;
        Bs[0][c][r] = (c < Cin) ? Xb[(size_t)(j0 + r)*ldx + c] : 0.f;
    }
    __syncthreads();
    for (int t = 0; t < T; t++) {
        int cur = t & 1, nxt = cur ^ 1;
        float pa[8], pb[4];
        if (t + 1 < T) {
            int k0n = (t + 1) << 4;
            #pragma unroll
            for (int n = 0; n < 8; n++) {
                int l = tid + 256*n; int r = l >> 4, c = l & 15; int kk = k0n + c;
                pa[n] = (kk < Cin) ? Xb[(size_t)(i0 + r)*ldx + kk] : 0.f;
            }
            #pragma unroll
            for (int n = 0; n < 4; n++) {
                int l = tid + 256*n; int r = l >> 4, c = l & 15; int kk = k0n + c;
                pb[n] = (kk < Cin) ? Xb[(size_t)(j0 + r)*ldx + kk] : 0.f;
            }
        }
        #pragma unroll
        for (int kk = 0; kk < 16; kk++) {
            float4 a0 = *(const float4*)&As[cur][kk][ty*8];
            float4 a1 = *(const float4*)&As[cur][kk][ty*8 + 4];
            float4 bq = *(const float4*)&Bs[cur][kk][tx*4];
            float a[8]  = {a0.x,a0.y,a0.z,a0.w,a1.x,a1.y,a1.z,a1.w};
            float bv[4] = {bq.x, bq.y, bq.z, bq.w};
            #pragma unroll
            for (int i = 0; i < 8; i++)
                #pragma unroll
                for (int j = 0; j < 4; j++)
                    acc[i][j] = __fmaf_rn(a[i], bv[j], acc[i][j]);
        }
        if (t + 1 < T) {
            #pragma unroll
            for (int n = 0; n < 8; n++) {
                int l = tid + 256*n; int r = l >> 4, c = l & 15;
                As[nxt][c][r] = pa[n];
            }
            #pragma unroll
            for (int n = 0; n < 4; n++) {
                int l = tid + 256*n; int r = l >> 4, c = l & 15;
                Bs[nxt][c][r] = pb[n];
            }
        }
        __syncthreads();
    }
    float* Sb = S + (size_t)b * NPT * NPT;
    const float* xxb = xx + (size_t)b * NPT;
    float4 xjq = *(const float4*)&xxb[j0 + tx*4];
    float xjv[4] = {xjq.x, xjq.y, xjq.z, xjq.w};
    #pragma unroll
    for (int i = 0; i < 8; i++) {
        float xi = xxb[i0 + ty*8 + i];
        float e[4];
        #pragma unroll
        for (int j = 0; j < 4; j++) {
            float inner = __fmul_rn(-2.f, acc[i][j]);
            float t1 = __fsub_rn(-xjv[j], inner);
            e[j] = __fsub_rn(t1, xi);
        }
        *(float4*)&Sb[(size_t)(i0 + ty*8 + i)*NPT + (j0 + tx*4)]
            = make_float4(e[0], e[1], e[2], e[3]);
    }
}

// ------------------------- top-k (warp per row, register-resident) ----------
// jax.lax.top_k semantics: values descending, ties broken by lowest index.
// Lane argmax via group-of-4 + tree-of-8 (prefer lower index on ties).
__global__ void topk_kernel(const float* __restrict__ S, int* __restrict__ idxout) {
    int gwarp = (blockIdx.x * blockDim.x + threadIdx.x) >> 5;
    int lane  = threadIdx.x & 31;
    if (gwarp >= NPTS_TOT) return;
    const float* row = S + (size_t)gwarp * NPT;

    float v[32];
    #pragma unroll
    for (int j = 0; j < 32; j++) v[j] = row[lane + (j << 5)];

    int* outp = idxout + (size_t)gwarp * KNN;
    for (int k = 0; k < KNN; k++) {
        float gv[8]; int gj[8];
        #pragma unroll
        for (int g = 0; g < 8; g++) {
            float bv_ = v[4*g]; int bj_ = 4*g;
            #pragma unroll
            for (int e = 1; e < 4; e++)
                if (v[4*g + e] > bv_) { bv_ = v[4*g + e]; bj_ = 4*g + e; }
            gv[g] = bv_; gj[g] = bj_;
        }
        #pragma unroll
        for (int st = 1; st < 8; st <<= 1)
            #pragma unroll
            for (int g = 0; g < 8; g += 2*st)
                if (gv[g + st] > gv[g]) { gv[g] = gv[g + st]; gj[g] = gj[g + st]; }
        float wv = gv[0];
        int   wm = lane + (gj[0] << 5);
        #pragma unroll
        for (int off = 16; off > 0; off >>= 1) {
            float ov = __shfl_xor_sync(0xffffffff, wv, off);
            int   om = __shfl_xor_sync(0xffffffff, wm, off);
            if (ov > wv || (ov == wv && om < wm)) { wv = ov; wm = om; }
        }
        if (lane == 0) outp[k] = wm;
        if ((wm & 31) == lane) {
            int jj = wm >> 5;
            #pragma unroll
            for (int j = 0; j < 32; j++)
                if (j == jj) v[j] = -FLTMAX;
        }
    }
}

// ------------------------- per-edge EXACT fp32 EdgeConv (L1-L3) -------------
// 256 threads = 8 warps; warp w owns point pt0+w (its 20 edges).
// lane: egsub = lane>>3 (4 groups of 5 edges), og = lane&7 (8 outs each).
// Per-(edge,out) ascending-fma chain identical to R10 -> features bit-identical.
// Stats reduce in-warp via shuffle (transient fp64 only, per-j; no reg arrays).
__global__ void edgeconv_kernel(const float* __restrict__ X, int ld, int Cin, int Cout,
                                const float* __restrict__ W,
                                const int* __restrict__ idx,
                                float* __restrict__ ymax, float* __restrict__ ymin,
                                double* __restrict__ chanSum, double* __restrict__ chanSqs) {
    __shared__ float  As[16][161];
    __shared__ float  Bs[16][68];
    __shared__ double wsum[8][64], wsq[8][64];
    __shared__ int sidx[160];
    int tid = threadIdx.x;
    int pt0 = blockIdx.x * 8;
    int o0  = blockIdx.y * 64;
    int brow = (pt0 / NPT) * NPT;
    if (tid < 160) sidx[tid] = idx[(size_t)(pt0 + tid/20)*KNN + tid%20];
    __syncthreads();
    int warp = tid >> 5, lane = tid & 31;
    int egsub = lane >> 3, og = lane & 7;
    float acc[5][8] = {};
    int C2 = 2*Cin;
    for (int k0 = 0; k0 < C2; k0 += 16) {
        #pragma unroll
        for (int n = 0; n < 4; n++) {
            int l = tid + 256*n; int r = l >> 4, c = l & 15;
            int cc = k0 + c;
            Bs[c][r] = (cc < C2) ? W[(size_t)(o0 + r)*C2 + cc] : 0.f;
        }
        #pragma unroll
        for (int n = 0; n < 10; n++) {
            int l = tid + 256*n; int r = l >> 4, c = l & 15;
            int cc = k0 + c;
            int p = r / 20;
            float v = 0.f;
            if (cc < Cin) {
                int m = sidx[r];
                v = __fsub_rn(X[(size_t)(brow + m)*ld + cc], X[(size_t)(pt0 + p)*ld + cc]);
            } else if (cc < C2) {
                v = X[(size_t)(pt0 + p)*ld + (cc - Cin)];
            }
            As[c][r] = v;
        }
        __syncthreads();
        #pragma unroll
        for (int kk = 0; kk < 16; kk++) {
            float a[5];
            #pragma unroll
            for (int i = 0; i < 5; i++) a[i] = As[kk][warp*20 + egsub*5 + i];
            float4 b0 = *(const float4*)&Bs[kk][og*8];
            float4 b1 = *(const float4*)&Bs[kk][og*8 + 4];
            float bv[8] = {b0.x,b0.y,b0.z,b0.w,b1.x,b1.y,b1.z,b1.w};
            #pragma unroll
            for (int i = 0; i < 5; i++)
                #pragma unroll
                for (int j = 0; j < 8; j++)
                    acc[i][j] = __fmaf_rn(a[i], bv[j], acc[i][j]);
        }
        __syncthreads();
    }
    // per-out stats over this warp's point (20 edges = 4 egsub x 5)
    #pragma unroll
    for (int j = 0; j < 8; j++) {
        float y0 = acc[0][j];
        float mx = y0, mn = y0;
        double s = (double)y0, q = (double)y0*(double)y0;
        #pragma unroll
        for (int i = 1; i < 5; i++) {
            float y = acc[i][j];
            mx = fmaxf(mx, y); mn = fminf(mn, y);
            s += (double)y; q += (double)y*(double)y;
        }
        mx = fmaxf(mx, __shfl_xor_sync(0xffffffff, mx, 8));
        mx = fmaxf(mx, __shfl_xor_sync(0xffffffff, mx, 16));
        mn = fminf(mn, __shfl_xor_sync(0xffffffff, mn, 8));
        mn = fminf(mn, __shfl_xor_sync(0xffffffff, mn, 16));
        s += __shfl_xor_sync(0xffffffff, s, 8);
        s += __shfl_xor_sync(0xffffffff, s, 16);
        q += __shfl_xor_sync(0xffffffff, q, 8);
        q += __shfl_xor_sync(0xffffffff, q, 16);
        if (lane < 8) {
            int oj = lane*8 + j;
            ymax[(size_t)(pt0 + warp)*Cout + o0 + oj] = mx;
            ymin[(size_t)(pt0 + warp)*Cout + o0 + oj] = mn;
            wsum[warp][oj] = s;
            wsq [warp][oj] = q;
        }
    }
    __syncthreads();
    if (tid < 64) {
        double S = 0.0, Q = 0.0;
        #pragma unroll
        for (int w = 0; w < 8; w++) { S += wsum[w][tid]; Q += wsq[w][tid]; }
        atomicAdd(&chanSum[o0 + tid], S);
        atomicAdd(&chanSqs[o0 + tid], Q);
    }
}

// ------------------------- L4 factorized gather -----------------------------
#define PPB 16
__global__ void gather_kernel(const float* __restrict__ PQ,
                              const int* __restrict__ idx,
                              float* __restrict__ ymax, float* __restrict__ ymin,
                              double* __restrict__ chanSum, double* __restrict__ chanSqs) {
    int o = threadIdx.x;                 // 256 = Cout
    int base = blockIdx.x * PPB;
    __shared__ int sidx[PPB][KNN];
    for (int l = o; l < PPB*KNN; l += 256)
        sidx[l/KNN][l%KNN] = idx[(size_t)(base + l/KNN)*KNN + l%KNN];
    __syncthreads();
    double s = 0.0, q = 0.0;
    for (int p = 0; p < PPB; p++) {
        int pt = base + p;
        int brow = (pt >> 10) << 10;
        float Qv = PQ[(size_t)pt*512 + 256 + o];
        float mx = -FLTMAX, mn = FLTMAX;
        #pragma unroll
        for (int k = 0; k < KNN; k++) {
            float y = __fadd_rn(PQ[(size_t)(brow + sidx[p][k])*512 + o], Qv);
            mx = fmaxf(mx, y); mn = fminf(mn, y);
            double yd = (double)y;
            s += yd; q += yd*yd;
        }
        ymax[(size_t)pt*256 + o] = mx;
        ymin[(size_t)pt*256 + o] = mn;
    }
    atomicAdd(&chanSum[o], s);
    atomicAdd(&chanSqs[o], q);
}

// out = lrelu(((v - m)*rs)*w + b), v = ymax if w>=0 else ymin — exact ref op order
__global__ void apply_edge_kernel(const float* __restrict__ ymax,
                                  const float* __restrict__ ymin,
                                  const float* __restrict__ M,
                                  const float* __restrict__ RS,
                                  const float* __restrict__ bw,
                                  const float* __restrict__ bb,
                                  int Cout, float* __restrict__ out, int ldo) {
    int o  = threadIdx.x;
    int pt = blockIdx.x;
    float w = bw[o];
    float v = (w >= 0.f) ? ymax[(size_t)pt*Cout + o] : ymin[(size_t)pt*Cout + o];
    float t = __fsub_rn(v, M[o]);
    t = __fmul_rn(t, RS[o]);
    t = __fmul_rn(t, w);
    t = __fadd_rn(t, bb[o]);
    out[(size_t)pt*ldo + o] = (t >= 0.f) ? t : __fmul_rn(NEG, t);
}

// ------------------------- conv5 stats + pooled reduce ----------------------
__global__ void y5stats_kernel(const float* __restrict__ Y5,
                               double* __restrict__ chanSum, double* __restrict__ chanSqs) {
    int cg = blockIdx.x * 64;
    int rg = blockIdx.y * 256;
    int t = threadIdx.x; int c = t % 64, ph = t / 64;
    double s = 0.0, sq = 0.0;
    for (int r = ph; r < 256; r += 4) {
        double v = (double)Y5[(size_t)(rg + r)*1024 + cg + c];
        s += v; sq += v*v;
    }
    __shared__ double ss[256], qq[256];
    ss[t] = s; qq[t] = sq; __syncthreads();
    if (ph == 0) {
        s  = ss[c] + ss[c+64] + ss[c+128] + ss[c+192];
        sq = qq[c] + qq[c+64] + qq[c+128] + qq[c+192];
        atomicAdd(&chanSum[cg+c], s);
        atomicAdd(&chanSqs[cg+c], sq);
    }
}

__global__ void y5reduce_kernel(const float* __restrict__ Y5,
                                const float* __restrict__ M, const float* __restrict__ RS,
                                const float* __restrict__ bw, const float* __restrict__ bb,
                                float* __restrict__ feat) {
    int cg = blockIdx.x * 64; int b = blockIdx.y;
    int t = threadIdx.x; int c = t % 64, ph = t / 64;
    float m = M[cg+c], rs = RS[cg+c], w = bw[cg+c], bbv = bb[cg+c];
    float mx = -FLTMAX, s = 0.f;
    for (int n = ph; n < NPT; n += 4) {
        float v = Y5[((size_t)b*NPT + n)*1024 + cg + c];
        float tv = __fsub_rn(v, m);
        tv = __fmul_rn(tv, rs);
        tv = __fmul_rn(tv, w);
        tv = __fadd_rn(tv, bbv);
        tv = (tv >= 0.f) ? tv : __fmul_rn(NEG, tv);
        mx = fmaxf(mx, tv); s += tv;
    }
    __shared__ float sm[256], ssum[256];
    sm[t] = mx; ssum[t] = s; __syncthreads();
    if (ph == 0) {
        mx = fmaxf(fmaxf(sm[c], sm[c+64]), fmaxf(sm[c+128], sm[c+192]));
        s  = ssum[c] + ssum[c+64] + ssum[c+128] + ssum[c+192];
        feat[(size_t)b*2048 + cg + c]        = mx;
        feat[(size_t)b*2048 + 1024 + cg + c] = __fdiv_rn(s, 1024.f);
    }
}

// ------------------------- head: linear + BN(batch=8) + lrelu ---------------
__global__ void head_kernel(const float* __restrict__ in, int Cin,
                            const float* __restrict__ W, const float* __restrict__ bias,
                            const float* __restrict__ bw, const float* __restrict__ bb,
                            float* __restrict__ out, int Cout) {
    int o = blockIdx.x;
    int t = threadIdx.x;
    float acc[8] = {0,0,0,0,0,0,0,0};
    for (int c = t; c < Cin; c += 256) {
        float w = W[(size_t)o*Cin + c];
        #pragma unroll
        for (int b = 0; b < 8; b++) acc[b] = __fmaf_rn(w, in[(size_t)b*Cin + c], acc[b]);
    }
    #pragma unroll
    for (int b = 0; b < 8; b++)
        #pragma unroll
        for (int off = 16; off > 0; off >>= 1)
            acc[b] += __shfl_xor_sync(0xffffffff, acc[b], off);
    __shared__ float ws[8][8];
    int warp = t >> 5, lane = t & 31;
    if (lane == 0)
        #pragma unroll
        for (int b = 0; b < 8; b++) ws[warp][b] = acc[b];
    __syncthreads();
    if (t == 0) {
        float z[8];
        #pragma unroll
        for (int b = 0; b < 8; b++) {
            float s = bias[o];
            #pragma unroll
            for (int w = 0; w < 8; w++) s += ws[w][b];
            z[b] = s;
        }
        float m = 0.f;
        #pragma unroll
        for (int b = 0; b < 8; b++) m += z[b];
        m *= 0.125f;
        float v = 0.f;
        #pragma unroll
        for (int b = 0; b < 8; b++) { float d = __fsub_rn(z[b], m); v = __fmaf_rn(d, d, v); }
        v *= 0.125f;
        float rs = rsqrtf(__fadd_rn(v, EPSB));
        #pragma unroll
        for (int b = 0; b < 8; b++) {
            float tt = __fsub_rn(z[b], m);
            tt = __fmul_rn(tt, rs);
            tt = __fmul_rn(tt, bw[o]);
            tt = __fadd_rn(tt, bb[o]);
            out[(size_t)b*Cout + o] = (tt >= 0.f) ? tt : __fmul_rn(NEG, tt);
        }
    }
}

__global__ void final_kernel(const float* __restrict__ H2, const float* __restrict__ W,
                             const float* __restrict__ bias, float* __restrict__ out) {
    int i = blockIdx.x * blockDim.x + threadIdx.x;
    if (i < 8*40) {
        int b = i / 40, o = i % 40;
        float s = bias[o];
        for (int c = 0; c < 256; c++)
            s = __fmaf_rn(H2[(size_t)b*256 + c], W[(size_t)o*256 + c], s);
        out[i] = s;
    }
}

// ------------------------- host driver --------------------------------------
extern "C" void kernel_launch(void* const* d_in, const int* in_sizes, int n_in,
                              void* d_out, int out_size) {
    const float* x   = (const float*)d_in[0];
    const float* c1w = (const float*)d_in[1];
    const float* c2w = (const float*)d_in[2];
    const float* c3w = (const float*)d_in[3];
    const float* c4w = (const float*)d_in[4];
    const float* c5w = (const float*)d_in[5];
    const float* bnw_[5] = { (const float*)d_in[6], (const float*)d_in[8],
                             (const float*)d_in[10], (const float*)d_in[12],
                             (const float*)d_in[14] };
    const float* bnb_[5] = { (const float*)d_in[7], (const float*)d_in[9],
                             (const float*)d_in[11], (const float*)d_in[13],
                             (const float*)d_in[15] };
    const float* b6w = (const float*)d_in[16];
    const float* b6b = (const float*)d_in[17];
    const float* b7w = (const float*)d_in[18];
    const float* b7b = (const float*)d_in[19];
    const float* l1w = (const float*)d_in[20];
    const float* l1b = (const float*)d_in[21];
    const float* l2w = (const float*)d_in[22];
    const float* l2b = (const float*)d_in[23];
    const float* l3w = (const float*)d_in[24];
    const float* l3b = (const float*)d_in[25];

    float *X0,*XX,*PD,*YMX,*YMN,*CAT,*Y5,*WC,*PQ,*M,*RS,*FEAT,*H1,*H2;
    double *SUM,*SQS;
    int *IDX;
    cudaGetSymbolAddress((void**)&X0,  g_X0);
    cudaGetSymbolAddress((void**)&XX,  g_XX);
    cudaGetSymbolAddress((void**)&PD,  g_PD);
    cudaGetSymbolAddress((void**)&IDX, g_IDX);
    cudaGetSymbolAddress((void**)&YMX, g_YMX);
    cudaGetSymbolAddress((void**)&YMN, g_YMN);
    cudaGetSymbolAddress((void**)&CAT, g_CAT);
    cudaGetSymbolAddress((void**)&Y5,  g_Y5);
    cudaGetSymbolAddress((void**)&WC,  g_WC);
    cudaGetSymbolAddress((void**)&PQ,  g_PQ);
    cudaGetSymbolAddress((void**)&SUM, g_SUM);
    cudaGetSymbolAddress((void**)&SQS, g_SQS);
    cudaGetSymbolAddress((void**)&M,   g_M);
    cudaGetSymbolAddress((void**)&RS,  g_RS);
    cudaGetSymbolAddress((void**)&FEAT,g_FEAT);
    cudaGetSymbolAddress((void**)&H1,  g_H1);
    cudaGetSymbolAddress((void**)&H2,  g_H2);

    transpose_x_kernel<<<(BSZ*NPT*3 + 255)/256, 256>>>(x, X0);

    const float* convW[4] = { c1w, c2w, c3w, c4w };
    int Cin [4] = { 3, 64, 64, 128 };
    int Cout[4] = { 64, 64, 128, 256 };
    int outOff[4] = { 0, 64, 128, 256 };

    for (int L = 0; L < 4; L++) {
        const float* Xin = (L == 0) ? X0 : (CAT + outOff[L-1]);
        int ldin = (L == 0) ? 3 : 512;
        int Ci = Cin[L], Co = Cout[L];

        rownorm_kernel<<<(NPTS_TOT + 255)/256, 256>>>(Xin, ldin, Ci, XX);
        dim3 ggrid(NPT/128, NPT/64, BSZ);
        gram_kernel<<<ggrid, 256>>>(Xin, ldin, Ci, XX, PD);
        topk_kernel<<<(NPTS_TOT*32)/256, 256>>>(PD, IDX);

        if (L < 3) {
            // exact per-edge path: output feeds the next layer's kNN
            dim3 egrid(NPTS_TOT/8, Co/64);
            edgeconv_kernel<<<egrid, 256>>>(Xin, ldin, Ci, Co, convW[L], IDX,
                                            YMX, YMN, SUM, SQS);
        } else {
            // L4 factorized path: no kNN downstream, value-tolerance only
            wcomb_kernel<<<(2*Co*Ci + 255)/256, 256>>>(convW[L], Ci, Co, WC);
            dim3 pqgrid(NPT/128, (2*Co)/64, BSZ);
            gemm_xw_kernel<<<pqgrid, 256>>>(Xin, ldin, Ci, WC, PQ, 2*Co);
            gather_kernel<<<NPTS_TOT/PPB, 256>>>(PQ, IDX, YMX, YMN, SUM, SQS);
        }

        bnfin_kernel<<<(Co + 255)/256, 256>>>(SUM, SQS,
                                              (double)(BSZ*NPT*KNN), Co, M, RS);
        apply_edge_kernel<<<NPTS_TOT, Co>>>(YMX, YMN, M, RS, bnw_[L], bnb_[L],
                                            Co, CAT + outOff[L], 512);
    }

    // conv5: Y5[b,n,o] = CAT[b,n,:] @ c5w[o,:]   (exact fp32, ascending K)
    dim3 g5(NPT/128, 1024/64, BSZ);
    gemm_xw_kernel<<<g5, 256>>>(CAT, 512, 512, c5w, Y5, 1024);
    dim3 sgrid(16, 32);
    y5stats_kernel<<<sgrid, 256>>>(Y5, SUM, SQS);
    bnfin_kernel<<<4, 256>>>(SUM, SQS, (double)(BSZ*NPT), 1024, M, RS);
    dim3 rgrid(16, BSZ);
    y5reduce_kernel<<<rgrid, 256>>>(Y5, M, RS, bnw_[4], bnb_[4], FEAT);

    head_kernel<<<512, 256>>>(FEAT, 2048, l1w, l1b, b6w, b6b, H1, 512);
    head_kernel<<<256, 256>>>(H1,   512,  l2w, l2b, b7w, b7b, H2, 256);
    final_kernel<<<2, 256>>>(H2, l3w, l3b, (float*)d_out);
}

// round 15
// speedup vs baseline: 1.0623x; 1.0623x over previous
#include <cuda_runtime.h>
#include <cstdint>

#define BSZ 8
#define NPT 1024
#define KNN 20
#define NEG 0.2f
#define EPSB 1e-5f
#define NPTS_TOT (BSZ*NPT)
#define FLTMAX 3.402823466e38f

// ------------------------- scratch (device globals; no allocs) -------------
__device__ float  g_X0 [BSZ*NPT*3];
__device__ float  g_XX [BSZ*NPT];
__device__ float  g_PD [BSZ*NPT*NPT];        // 32 MB pairwise scores
__device__ int    g_IDX[BSZ*NPT*KNN];
__device__ float  g_YMX[BSZ*NPT*256];
__device__ float  g_YMN[BSZ*NPT*256];
__device__ float  g_CAT[BSZ*NPT*512];        // x1|x2|x3|x4 per point row
__device__ float  g_Y5 [BSZ*NPT*1024];       // 32 MB conv5 output
__device__ float  g_WC [512*128];            // L4 combined [W1; W2-W1]
__device__ float  g_PQ [BSZ*NPT*512];        // L4 [P | Q] per point (16 MB)
__device__ double g_SUM[1024];               // zero-init at load; bnfin re-zeroes
__device__ double g_SQS[1024];
__device__ float  g_M  [1024];
__device__ float  g_RS [1024];
__device__ float  g_FEAT[BSZ*2048];
__device__ float  g_H1 [BSZ*512];
__device__ float  g_H2 [BSZ*256];

// ------------------------- small utility kernels ---------------------------
__global__ void transpose_x_kernel(const float* __restrict__ x, float* __restrict__ X0) {
    int i = blockIdx.x * blockDim.x + threadIdx.x;
    if (i < BSZ*NPT*3) {
        int b = i / (NPT*3); int rest = i % (NPT*3);
        int n = rest / 3, c = rest % 3;
        X0[i] = x[((size_t)b*3 + c)*NPT + n];
    }
}

// xx[n] = sum_c x[n,c]^2  — square rounded, then ascending adds (NO fma)
__global__ void rownorm_kernel(const float* __restrict__ X, int ld, int Cin,
                               float* __restrict__ xx) {
    int pt = blockIdx.x * blockDim.x + threadIdx.x;
    if (pt < NPTS_TOT) {
        const float* r = X + (size_t)pt * ld;
        float s = 0.f;
        for (int c = 0; c < Cin; c++) {
            float v = r[c];
            s = __fadd_rn(s, __fmul_rn(v, v));
        }
        xx[pt] = s;
    }
}

// L4 combined weights: WC[o] = W1[o]; WC[Cout+o] = W2[o]-W1[o]
__global__ void wcomb_kernel(const float* __restrict__ W, int Cin, int Cout,
                             float* __restrict__ WC) {
    int i = blockIdx.x * blockDim.x + threadIdx.x;
    if (i < 2*Cout*Cin) {
        int o = i / Cin, c = i % Cin;
        if (o < Cout) WC[i] = W[(size_t)o*(2*Cin) + c];
        else {
            int oo = o - Cout;
            WC[i] = __fsub_rn(W[(size_t)oo*(2*Cin) + Cin + c],
                              W[(size_t)oo*(2*Cin) + c]);
        }
    }
}

// From fp64 sums: m, rs — then RE-ZEROES the stats slots for the next phase.
__global__ void bnfin_kernel(double* __restrict__ sum, double* __restrict__ sqs,
                             double cnt, int C,
                             float* __restrict__ M, float* __restrict__ RS) {
    int o = blockIdx.x * blockDim.x + threadIdx.x;
    if (o < C) {
        double mu = sum[o] / cnt;
        float m = (float)mu;
        double vd = sqs[o]/cnt - 2.0*(double)m*mu + (double)m*(double)m;
        float v = (float)vd;
        M[o]  = m;
        RS[o] = rsqrtf(__fadd_rn(v, EPSB));
        sum[o] = 0.0;
        sqs[o] = 0.0;
    }
}

// ------------------------- tiled fp32 GEMM (128x128, 256 thr, 8x8, dbuf) ---
// Used ONLY on the value-tolerant path (conv5, L4 PQ) — but per-output
// ascending-k single-accumulator fma chain is unchanged => bit-identical.
// Micro-tile split (4+4)x(4+4) keeps every LDS.128 conflict-free.
__global__ void __launch_bounds__(256, 2)
gemm_xw_kernel(const float* __restrict__ X, int ldx, int Cin,
               const float* __restrict__ W,
               float* __restrict__ out, int ldo) {
    int b  = blockIdx.z;
    int i0 = blockIdx.x * 128;
    int j0 = blockIdx.y * 128;
    __shared__ float As[2][16][132];
    __shared__ float Bs[2][16][132];
    int tid = threadIdx.x, tx = tid % 16, ty = tid / 16;
    float acc[8][8] = {};
    const float* Xb = X + (size_t)b * NPT * ldx;
    int T = (Cin + 15) >> 4;
    #pragma unroll
    for (int n = 0; n < 8; n++) {
        int l = tid + 256*n; int r = l >> 4, c = l & 15;
        As[0][c][r] = (c < Cin) ? Xb[(size_t)(i0 + r)*ldx + c] : 0.f;
        Bs[0][c][r] = (c < Cin) ? W [(size_t)(j0 + r)*Cin + c] : 0.f;
    }
    __syncthreads();
    for (int t = 0; t < T; t++) {
        int cur = t & 1, nxt = cur ^ 1;
        float pa[8], pb[8];
        if (t + 1 < T) {
            int k0n = (t + 1) << 4;
            #pragma unroll
            for (int n = 0; n < 8; n++) {
                int l = tid + 256*n; int r = l >> 4, c = l & 15; int kk = k0n + c;
                pa[n] = (kk < Cin) ? Xb[(size_t)(i0 + r)*ldx + kk] : 0.f;
                pb[n] = (kk < Cin) ? W [(size_t)(j0 + r)*Cin + kk] : 0.f;
            }
        }
        #pragma unroll
        for (int kk = 0; kk < 16; kk++) {
            float4 a0 = *(const float4*)&As[cur][kk][ty*4];
            float4 a1 = *(const float4*)&As[cur][kk][64 + ty*4];
            float4 b0 = *(const float4*)&Bs[cur][kk][tx*4];
            float4 b1 = *(const float4*)&Bs[cur][kk][64 + tx*4];
            float a[8]  = {a0.x,a0.y,a0.z,a0.w,a1.x,a1.y,a1.z,a1.w};
            float bv[8] = {b0.x,b0.y,b0.z,b0.w,b1.x,b1.y,b1.z,b1.w};
            #pragma unroll
            for (int i = 0; i < 8; i++)
                #pragma unroll
                for (int j = 0; j < 8; j++)
                    acc[i][j] = __fmaf_rn(a[i], bv[j], acc[i][j]);
        }
        if (t + 1 < T) {
            #pragma unroll
            for (int n = 0; n < 8; n++) {
                int l = tid + 256*n; int r = l >> 4, c = l & 15;
                As[nxt][c][r] = pa[n];
                Bs[nxt][c][r] = pb[n];
            }
        }
        __syncthreads();
    }
    float* outb = out + (size_t)b * NPT * ldo;
    #pragma unroll
    for (int i = 0; i < 8; i++) {
        int row = i0 + ((i < 4) ? (ty*4 + i) : (64 + ty*4 + i - 4));
        *(float4*)&outb[(size_t)row*ldo + (j0 + tx*4)]
            = make_float4(acc[i][0], acc[i][1], acc[i][2], acc[i][3]);
        *(float4*)&outb[(size_t)row*ldo + (j0 + 64 + tx*4)]
            = make_float4(acc[i][4], acc[i][5], acc[i][6], acc[i][7]);
    }
}

// pd[b,i,j] = (-xx[j] - (-2*dot_ij)) - xx[i], dot via ascending fma (exact fp32)
// R10 configuration: 128x64 tile, 8x4 micro, double-buffered.
__global__ void gram_kernel(const float* __restrict__ X, int ldx, int Cin,
                            const float* __restrict__ xx, float* __restrict__ S) {
    int b  = blockIdx.z;
    int i0 = blockIdx.x * 128;
    int j0 = blockIdx.y * 64;
    __shared__ float As[2][16][132];
    __shared__ float Bs[2][16][68];
    int tid = threadIdx.x, tx = tid % 16, ty = tid / 16;
    float acc[8][4] = {};
    const float* Xb = X + (size_t)b * NPT * ldx;
    int T = (Cin + 15) >> 4;
    #pragma unroll
    for (int n = 0; n < 8; n++) {
        int l = tid + 256*n; int r = l >> 4, c = l & 15;
        As[0][c][r] = (c < Cin) ? Xb[(size_t)(i0 + r)*ldx + c] : 0.f;
    }
    #pragma unroll
    for (int n = 0; n < 4; n++) {
        int l = tid + 256*n; int r = l >> 4, c = l & 15;
        Bs[0][c][r] = (c < Cin) ? Xb[(size_t)(j0 + r)*ldx + c] : 0.f;
    }
    __syncthreads();
    for (int t = 0; t < T; t++) {
        int cur = t & 1, nxt = cur ^ 1;
        float pa[8], pb[4];
        if (t + 1 < T) {
            int k0n = (t + 1) << 4;
            #pragma unroll
            for (int n = 0; n < 8; n++) {
                int l = tid + 256*n; int r = l >> 4, c = l & 15; int kk = k0n + c;
                pa[n] = (kk < Cin) ? Xb[(size_t)(i0 + r)*ldx + kk] : 0.f;
            }
            #pragma unroll
            for (int n = 0; n < 4; n++) {
                int l = tid + 256*n; int r = l >> 4, c = l & 15; int kk = k0n + c;
                pb[n] = (kk < Cin) ? Xb[(size_t)(j0 + r)*ldx + kk] : 0.f;
            }
        }
        #pragma unroll
        for (int kk = 0; kk < 16; kk++) {
            float4 a0 = *(const float4*)&As[cur][kk][ty*8];
            float4 a1 = *(const float4*)&As[cur][kk][ty*8 + 4];
            float4 bq = *(const float4*)&Bs[cur][kk][tx*4];
            float a[8]  = {a0.x,a0.y,a0.z,a0.w,a1.x,a1.y,a1.z,a1.w};
            float bv[4] = {bq.x, bq.y, bq.z, bq.w};
            #pragma unroll
            for (int i = 0; i < 8; i++)
                #pragma unroll
                for (int j = 0; j < 4; j++)
                    acc[i][j] = __fmaf_rn(a[i], bv[j], acc[i][j]);
        }
        if (t + 1 < T) {
            #pragma unroll
            for (int n = 0; n < 8; n++) {
                int l = tid + 256*n; int r = l >> 4, c = l & 15;
                As[nxt][c][r] = pa[n];
            }
            #pragma unroll
            for (int n = 0; n < 4; n++) {
                int l = tid + 256*n; int r = l >> 4, c = l & 15;
                Bs[nxt][c][r] = pb[n];
            }
        }
        __syncthreads();
    }
    float* Sb = S + (size_t)b * NPT * NPT;
    const float* xxb = xx + (size_t)b * NPT;
    float4 xjq = *(const float4*)&xxb[j0 + tx*4];
    float xjv[4] = {xjq.x, xjq.y, xjq.z, xjq.w};
    #pragma unroll
    for (int i = 0; i < 8; i++) {
        float xi = xxb[i0 + ty*8 + i];
        float e[4];
        #pragma unroll
        for (int j = 0; j < 4; j++) {
            float inner = __fmul_rn(-2.f, acc[i][j]);
            float t1 = __fsub_rn(-xjv[j], inner);
            e[j] = __fsub_rn(t1, xi);
        }
        *(float4*)&Sb[(size_t)(i0 + ty*8 + i)*NPT + (j0 + tx*4)]
            = make_float4(e[0], e[1], e[2], e[3]);
    }
}

// ------------------------- top-k (warp per row, register-resident) ----------
// jax.lax.top_k semantics: values descending, ties broken by lowest index.
// Lane argmax via group-of-4 + tree-of-8 (prefer lower index on ties).
__global__ void topk_kernel(const float* __restrict__ S, int* __restrict__ idxout) {
    int gwarp = (blockIdx.x * blockDim.x + threadIdx.x) >> 5;
    int lane  = threadIdx.x & 31;
    if (gwarp >= NPTS_TOT) return;
    const float* row = S + (size_t)gwarp * NPT;

    float v[32];
    #pragma unroll
    for (int j = 0; j < 32; j++) v[j] = row[lane + (j << 5)];

    int* outp = idxout + (size_t)gwarp * KNN;
    for (int k = 0; k < KNN; k++) {
        float gv[8]; int gj[8];
        #pragma unroll
        for (int g = 0; g < 8; g++) {
            float bv_ = v[4*g]; int bj_ = 4*g;
            #pragma unroll
            for (int e = 1; e < 4; e++)
                if (v[4*g + e] > bv_) { bv_ = v[4*g + e]; bj_ = 4*g + e; }
            gv[g] = bv_; gj[g] = bj_;
        }
        #pragma unroll
        for (int st = 1; st < 8; st <<= 1)
            #pragma unroll
            for (int g = 0; g < 8; g += 2*st)
                if (gv[g + st] > gv[g]) { gv[g] = gv[g + st]; gj[g] = gj[g + st]; }
        float wv = gv[0];
        int   wm = lane + (gj[0] << 5);
        #pragma unroll
        for (int off = 16; off > 0; off >>= 1) {
            float ov = __shfl_xor_sync(0xffffffff, wv, off);
            int   om = __shfl_xor_sync(0xffffffff, wm, off);
            if (ov > wv || (ov == wv && om < wm)) { wv = ov; wm = om; }
        }
        if (lane == 0) outp[k] = wm;
        if ((wm & 31) == lane) {
            int jj = wm >> 5;
            #pragma unroll
            for (int j = 0; j < 32; j++)
                if (j == jj) v[j] = -FLTMAX;
        }
    }
}

// ------------------------- per-edge EXACT fp32 EdgeConv (L1-L3, R10) --------
// y[edge,o] = ascending-fma dot of f=[nbr-ctr | ctr] with W[o,:]. 80 edges
// (4 pts) x 64 outs per block; warp w == point w; shuffle-reduced stats.
__global__ void edgeconv_kernel(const float* __restrict__ X, int ld, int Cin, int Cout,
                                const float* __restrict__ W,
                                const int* __restrict__ idx,
                                float* __restrict__ ymax, float* __restrict__ ymin,
                                double* __restrict__ chanSum, double* __restrict__ chanSqs) {
    __shared__ float  As[16][81];
    __shared__ float  Bs[16][68];
    __shared__ double wsum[4][64], wsq[4][64];
    __shared__ int sidx[80];
    int tid = threadIdx.x;
    int pt0 = blockIdx.x * 4;
    int o0  = blockIdx.y * 64;
    int brow = (pt0 / NPT) * NPT;
    if (tid < 80) sidx[tid] = idx[(size_t)(pt0 + tid/20)*KNN + tid%20];
    __syncthreads();
    int eg = tid >> 3;          // 0..15 (5 edges each; warp w holds eg 4w..4w+3 = point w)
    int og = tid & 7;           // 0..7  (8 outs each)
    int warp = tid >> 5, lane = tid & 31;
    float acc[5][8] = {};
    int C2 = 2*Cin;
    for (int k0 = 0; k0 < C2; k0 += 16) {
        for (int l = tid; l < 64*16; l += 128) {
            int r = l >> 4, c = l & 15;
            int cc = k0 + c;
            Bs[c][r] = (cc < C2) ? W[(size_t)(o0 + r)*C2 + cc] : 0.f;
        }
        for (int l = tid; l < 80*16; l += 128) {
            int r = l >> 4, c = l & 15;
            int cc = k0 + c;
            int p = r / 20;
            float v = 0.f;
            if (cc < Cin) {
                int m = sidx[r];
                v = __fsub_rn(X[(size_t)(brow + m)*ld + cc], X[(size_t)(pt0 + p)*ld + cc]);
            } else if (cc < C2) {
                v = X[(size_t)(pt0 + p)*ld + (cc - Cin)];
            }
            As[c][r] = v;
        }
        __syncthreads();
        #pragma unroll
        for (int kk = 0; kk < 16; kk++) {
            float a[5];
            #pragma unroll
            for (int i = 0; i < 5; i++) a[i] = As[kk][eg*5 + i];
            float4 b0 = *(const float4*)&Bs[kk][og*8];
            float4 b1 = *(const float4*)&Bs[kk][og*8 + 4];
            float bv[8] = {b0.x,b0.y,b0.z,b0.w,b1.x,b1.y,b1.z,b1.w};
            #pragma unroll
            for (int i = 0; i < 5; i++)
                #pragma unroll
                for (int j = 0; j < 8; j++)
                    acc[i][j] = __fmaf_rn(a[i], bv[j], acc[i][j]);
        }
        __syncthreads();
    }
    #pragma unroll
    for (int j = 0; j < 8; j++) {
        float y0 = acc[0][j];
        float mx = y0, mn = y0;
        double s = (double)y0, q = (double)y0*(double)y0;
        #pragma unroll
        for (int i = 1; i < 5; i++) {
            float y = acc[i][j];
            mx = fmaxf(mx, y); mn = fminf(mn, y);
            s += (double)y; q += (double)y*(double)y;
        }
        mx = fmaxf(mx, __shfl_xor_sync(0xffffffff, mx, 8));
        mx = fmaxf(mx, __shfl_xor_sync(0xffffffff, mx, 16));
        mn = fminf(mn, __shfl_xor_sync(0xffffffff, mn, 8));
        mn = fminf(mn, __shfl_xor_sync(0xffffffff, mn, 16));
        s += __shfl_xor_sync(0xffffffff, s, 8);
        s += __shfl_xor_sync(0xffffffff, s, 16);
        q += __shfl_xor_sync(0xffffffff, q, 8);
        q += __shfl_xor_sync(0xffffffff, q, 16);
        if (lane < 8) {
            int oj = lane*8 + j;
            ymax[(size_t)(pt0 + warp)*Cout + o0 + oj] = mx;
            ymin[(size_t)(pt0 + warp)*Cout + o0 + oj] = mn;
            wsum[warp][oj] = s;
            wsq [warp][oj] = q;
        }
    }
    __syncthreads();
    if (tid < 64) {
        double S = wsum[0][tid] + wsum[1][tid] + wsum[2][tid] + wsum[3][tid];
        double Q = wsq [0][tid] + wsq [1][tid] + wsq [2][tid] + wsq [3][tid];
        atomicAdd(&chanSum[o0 + tid], S);
        atomicAdd(&chanSqs[o0 + tid], Q);
    }
}

// ------------------------- L4 factorized gather -----------------------------
#define PPB 16
__global__ void gather_kernel(const float* __restrict__ PQ,
                              const int* __restrict__ idx,
                              float* __restrict__ ymax, float* __restrict__ ymin,
                              double* __restrict__ chanSum, double* __restrict__ chanSqs) {
    int o = threadIdx.x;                 // 256 = Cout
    int base = blockIdx.x * PPB;
    __shared__ int sidx[PPB][KNN];
    for (int l = o; l < PPB*KNN; l += 256)
        sidx[l/KNN][l%KNN] = idx[(size_t)(base + l/KNN)*KNN + l%KNN];
    __syncthreads();
    double s = 0.0, q = 0.0;
    for (int p = 0; p < PPB; p++) {
        int pt = base + p;
        int brow = (pt >> 10) << 10;
        float Qv = PQ[(size_t)pt*512 + 256 + o];
        float mx = -FLTMAX, mn = FLTMAX;
        #pragma unroll
        for (int k = 0; k < KNN; k++) {
            float y = __fadd_rn(PQ[(size_t)(brow + sidx[p][k])*512 + o], Qv);
            mx = fmaxf(mx, y); mn = fminf(mn, y);
            double yd = (double)y;
            s += yd; q += yd*yd;
        }
        ymax[(size_t)pt*256 + o] = mx;
        ymin[(size_t)pt*256 + o] = mn;
    }
    atomicAdd(&chanSum[o], s);
    atomicAdd(&chanSqs[o], q);
}

// out = lrelu(((v - m)*rs)*w + b), v = ymax if w>=0 else ymin — exact ref op order
__global__ void apply_edge_kernel(const float* __restrict__ ymax,
                                  const float* __restrict__ ymin,
                                  const float* __restrict__ M,
                                  const float* __restrict__ RS,
                                  const float* __restrict__ bw,
                                  const float* __restrict__ bb,
                                  int Cout, float* __restrict__ out, int ldo) {
    int o  = threadIdx.x;
    int pt = blockIdx.x;
    float w = bw[o];
    float v = (w >= 0.f) ? ymax[(size_t)pt*Cout + o] : ymin[(size_t)pt*Cout + o];
    float t = __fsub_rn(v, M[o]);
    t = __fmul_rn(t, RS[o]);
    t = __fmul_rn(t, w);
    t = __fadd_rn(t, bb[o]);
    out[(size_t)pt*ldo + o] = (t >= 0.f) ? t : __fmul_rn(NEG, t);
}

// ------------------------- conv5 stats + pooled reduce ----------------------
__global__ void y5stats_kernel(const float* __restrict__ Y5,
                               double* __restrict__ chanSum, double* __restrict__ chanSqs) {
    int cg = blockIdx.x * 64;
    int rg = blockIdx.y * 256;
    int t = threadIdx.x; int c = t % 64, ph = t / 64;
    double s = 0.0, sq = 0.0;
    for (int r = ph; r < 256; r += 4) {
        double v = (double)Y5[(size_t)(rg + r)*1024 + cg + c];
        s += v; sq += v*v;
    }
    __shared__ double ss[256], qq[256];
    ss[t] = s; qq[t] = sq; __syncthreads();
    if (ph == 0) {
        s  = ss[c] + ss[c+64] + ss[c+128] + ss[c+192];
        sq = qq[c] + qq[c+64] + qq[c+128] + qq[c+192];
        atomicAdd(&chanSum[cg+c], s);
        atomicAdd(&chanSqs[cg+c], sq);
    }
}

__global__ void y5reduce_kernel(const float* __restrict__ Y5,
                                const float* __restrict__ M, const float* __restrict__ RS,
                                const float* __restrict__ bw, const float* __restrict__ bb,
                                float* __restrict__ feat) {
    int cg = blockIdx.x * 64; int b = blockIdx.y;
    int t = threadIdx.x; int c = t % 64, ph = t / 64;
    float m = M[cg+c], rs = RS[cg+c], w = bw[cg+c], bbv = bb[cg+c];
    float mx = -FLTMAX, s = 0.f;
    for (int n = ph; n < NPT; n += 4) {
        float v = Y5[((size_t)b*NPT + n)*1024 + cg + c];
        float tv = __fsub_rn(v, m);
        tv = __fmul_rn(tv, rs);
        tv = __fmul_rn(tv, w);
        tv = __fadd_rn(tv, bbv);
        tv = (tv >= 0.f) ? tv : __fmul_rn(NEG, tv);
        mx = fmaxf(mx, tv); s += tv;
    }
    __shared__ float sm[256], ssum[256];
    sm[t] = mx; ssum[t] = s; __syncthreads();
    if (ph == 0) {
        mx = fmaxf(fmaxf(sm[c], sm[c+64]), fmaxf(sm[c+128], sm[c+192]));
        s  = ssum[c] + ssum[c+64] + ssum[c+128] + ssum[c+192];
        feat[(size_t)b*2048 + cg + c]        = mx;
        feat[(size_t)b*2048 + 1024 + cg + c] = __fdiv_rn(s, 1024.f);
    }
}

// ------------------------- head: linear + BN(batch=8) + lrelu ---------------
__global__ void head_kernel(const float* __restrict__ in, int Cin,
                            const float* __restrict__ W, const float* __restrict__ bias,
                            const float* __restrict__ bw, const float* __restrict__ bb,
                            float* __restrict__ out, int Cout) {
    int o = blockIdx.x;
    int t = threadIdx.x;
    float acc[8] = {0,0,0,0,0,0,0,0};
    for (int c = t; c < Cin; c += 256) {
        float w = W[(size_t)o*Cin + c];
        #pragma unroll
        for (int b = 0; b < 8; b++) acc[b] = __fmaf_rn(w, in[(size_t)b*Cin + c], acc[b]);
    }
    #pragma unroll
    for (int b = 0; b < 8; b++)
        #pragma unroll
        for (int off = 16; off > 0; off >>= 1)
            acc[b] += __shfl_xor_sync(0xffffffff, acc[b], off);
    __shared__ float ws[8][8];
    int warp = t >> 5, lane = t & 31;
    if (lane == 0)
        #pragma unroll
        for (int b = 0; b < 8; b++) ws[warp][b] = acc[b];
    __syncthreads();
    if (t == 0) {
        float z[8];
        #pragma unroll
        for (int b = 0; b < 8; b++) {
            float s = bias[o];
            #pragma unroll
            for (int w = 0; w < 8; w++) s += ws[w][b];
            z[b] = s;
        }
        float m = 0.f;
        #pragma unroll
        for (int b = 0; b < 8; b++) m += z[b];
        m *= 0.125f;
        float v = 0.f;
        #pragma unroll
        for (int b = 0; b < 8; b++) { float d = __fsub_rn(z[b], m); v = __fmaf_rn(d, d, v); }
        v *= 0.125f;
        float rs = rsqrtf(__fadd_rn(v, EPSB));
        #pragma unroll
        for (int b = 0; b < 8; b++) {
            float tt = __fsub_rn(z[b], m);
            tt = __fmul_rn(tt, rs);
            tt = __fmul_rn(tt, bw[o]);
            tt = __fadd_rn(tt, bb[o]);
            out[(size_t)b*Cout + o] = (tt >= 0.f) ? tt : __fmul_rn(NEG, tt);
        }
    }
}

__global__ void final_kernel(const float* __restrict__ H2, const float* __restrict__ W,
                             const float* __restrict__ bias, float* __restrict__ out) {
    int i = blockIdx.x * blockDim.x + threadIdx.x;
    if (i < 8*40) {
        int b = i / 40, o = i % 40;
        float s = bias[o];
        for (int c = 0; c < 256; c++)
            s = __fmaf_rn(H2[(size_t)b*256 + c], W[(size_t)o*256 + c], s);
        out[i] = s;
    }
}

// ------------------------- host driver --------------------------------------
extern "C" void kernel_launch(void* const* d_in, const int* in_sizes, int n_in,
                              void* d_out, int out_size) {
    const float* x   = (const float*)d_in[0];
    const float* c1w = (const float*)d_in[1];
    const float* c2w = (const float*)d_in[2];
    const float* c3w = (const float*)d_in[3];
    const float* c4w = (const float*)d_in[4];
    const float* c5w = (const float*)d_in[5];
    const float* bnw_[5] = { (const float*)d_in[6], (const float*)d_in[8],
                             (const float*)d_in[10], (const float*)d_in[12],
                             (const float*)d_in[14] };
    const float* bnb_[5] = { (const float*)d_in[7], (const float*)d_in[9],
                             (const float*)d_in[11], (const float*)d_in[13],
                             (const float*)d_in[15] };
    const float* b6w = (const float*)d_in[16];
    const float* b6b = (const float*)d_in[17];
    const float* b7w = (const float*)d_in[18];
    const float* b7b = (const float*)d_in[19];
    const float* l1w = (const float*)d_in[20];
    const float* l1b = (const float*)d_in[21];
    const float* l2w = (const float*)d_in[22];
    const float* l2b = (const float*)d_in[23];
    const float* l3w = (const float*)d_in[24];
    const float* l3b = (const float*)d_in[25];

    float *X0,*XX,*PD,*YMX,*YMN,*CAT,*Y5,*WC,*PQ,*M,*RS,*FEAT,*H1,*H2;
    double *SUM,*SQS;
    int *IDX;
    cudaGetSymbolAddress((void**)&X0,  g_X0);
    cudaGetSymbolAddress((void**)&XX,  g_XX);
    cudaGetSymbolAddress((void**)&PD,  g_PD);
    cudaGetSymbolAddress((void**)&IDX, g_IDX);
    cudaGetSymbolAddress((void**)&YMX, g_YMX);
    cudaGetSymbolAddress((void**)&YMN, g_YMN);
    cudaGetSymbolAddress((void**)&CAT, g_CAT);
    cudaGetSymbolAddress((void**)&Y5,  g_Y5);
    cudaGetSymbolAddress((void**)&WC,  g_WC);
    cudaGetSymbolAddress((void**)&PQ,  g_PQ);
    cudaGetSymbolAddress((void**)&SUM, g_SUM);
    cudaGetSymbolAddress((void**)&SQS, g_SQS);
    cudaGetSymbolAddress((void**)&M,   g_M);
    cudaGetSymbolAddress((void**)&RS,  g_RS);
    cudaGetSymbolAddress((void**)&FEAT,g_FEAT);
    cudaGetSymbolAddress((void**)&H1,  g_H1);
    cudaGetSymbolAddress((void**)&H2,  g_H2);

    transpose_x_kernel<<<(BSZ*NPT*3 + 255)/256, 256>>>(x, X0);

    const float* convW[4] = { c1w, c2w, c3w, c4w };
    int Cin [4] = { 3, 64, 64, 128 };
    int Cout[4] = { 64, 64, 128, 256 };
    int outOff[4] = { 0, 64, 128, 256 };

    for (int L = 0; L < 4; L++) {
        const float* Xin = (L == 0) ? X0 : (CAT + outOff[L-1]);
        int ldin = (L == 0) ? 3 : 512;
        int Ci = Cin[L], Co = Cout[L];

        rownorm_kernel<<<(NPTS_TOT + 255)/256, 256>>>(Xin, ldin, Ci, XX);
        dim3 ggrid(NPT/128, NPT/64, BSZ);
        gram_kernel<<<ggrid, 256>>>(Xin, ldin, Ci, XX, PD);
        topk_kernel<<<(NPTS_TOT*32)/256, 256>>>(PD, IDX);

        if (L < 3) {
            // exact per-edge path: output feeds the next layer's kNN
            dim3 egrid(NPTS_TOT/4, Co/64);
            edgeconv_kernel<<<egrid, 128>>>(Xin, ldin, Ci, Co, convW[L], IDX,
                                            YMX, YMN, SUM, SQS);
        } else {
            // L4 factorized path: no kNN downstream, value-tolerance only
            wcomb_kernel<<<(2*Co*Ci + 255)/256, 256>>>(convW[L], Ci, Co, WC);
            dim3 pqgrid(NPT/128, (2*Co)/128, BSZ);
            gemm_xw_kernel<<<pqgrid, 256>>>(Xin, ldin, Ci, WC, PQ, 2*Co);
            gather_kernel<<<NPTS_TOT/PPB, 256>>>(PQ, IDX, YMX, YMN, SUM, SQS);
        }

        bnfin_kernel<<<(Co + 255)/256, 256>>>(SUM, SQS,
                                              (double)(BSZ*NPT*KNN), Co, M, RS);
        apply_edge_kernel<<<NPTS_TOT, Co>>>(YMX, YMN, M, RS, bnw_[L], bnb_[L],
                                            Co, CAT + outOff[L], 512);
    }

    // conv5: Y5[b,n,o] = CAT[b,n,:] @ c5w[o,:]   (exact fp32, ascending K)
    dim3 g5(NPT/128, 1024/128, BSZ);
    gemm_xw_kernel<<<g5, 256>>>(CAT, 512, 512, c5w, Y5, 1024);
    dim3 sgrid(16, 32);
    y5stats_kernel<<<sgrid, 256>>>(Y5, SUM, SQS);
    bnfin_kernel<<<4, 256>>>(SUM, SQS, (double)(BSZ*NPT), 1024, M, RS);
    dim3 rgrid(16, BSZ);
    y5reduce_kernel<<<rgrid, 256>>>(Y5, M, RS, bnw_[4], bnb_[4], FEAT);

    head_kernel<<<512, 256>>>(FEAT, 2048, l1w, l1b, b6w, b6b, H1, 512);
    head_kernel<<<256, 256>>>(H1,   512,  l2w, l2b, b7w, b7b, H2, 256);
    final_kernel<<<2, 256>>>(H2, l3w, l3b, (float*)d_out);
}

// round 16
// speedup vs baseline: 1.0937x; 1.0296x over previous
#include <cuda_runtime.h>
#include <cstdint>

#define BSZ 8
#define NPT 1024
#define KNN 20
#define NEG 0.2f
#define EPSB 1e-5f
#define NPTS_TOT (BSZ*NPT)
#define FLTMAX 3.402823466e38f

// ------------------------- scratch (device globals; no allocs) -------------
__device__ float  g_X0 [BSZ*NPT*3];
__device__ float  g_XX [BSZ*NPT];
__device__ float  g_PD [BSZ*NPT*NPT];        // 32 MB pairwise scores
__device__ int    g_IDX[BSZ*NPT*KNN];
__device__ float  g_YMX[BSZ*NPT*256];
__device__ float  g_YMN[BSZ*NPT*256];
__device__ float  g_CAT[BSZ*NPT*512];        // x1|x2|x3|x4 per point row
__device__ float  g_Y5 [BSZ*NPT*1024];       // 32 MB conv5 output
__device__ float  g_WC [512*128];            // L4 combined [W1; W2-W1]
__device__ float  g_PQ [BSZ*NPT*512];        // L4 [P | Q] per point (16 MB)
__device__ double g_SUM[1024];               // zero-init at load; bnfin re-zeroes
__device__ double g_SQS[1024];
__device__ float  g_M  [1024];
__device__ float  g_RS [1024];
__device__ float  g_FEAT[BSZ*2048];
__device__ float  g_H1 [BSZ*512];
__device__ float  g_H2 [BSZ*256];

// ------------------------- small utility kernels ---------------------------
__global__ void transpose_x_kernel(const float* __restrict__ x, float* __restrict__ X0) {
    int i = blockIdx.x * blockDim.x + threadIdx.x;
    if (i < BSZ*NPT*3) {
        int b = i / (NPT*3); int rest = i % (NPT*3);
        int n = rest / 3, c = rest % 3;
        X0[i] = x[((size_t)b*3 + c)*NPT + n];
    }
}

// xx[n] = sum_c x[n,c]^2  — square rounded, then ascending adds (NO fma)
__global__ void rownorm_kernel(const float* __restrict__ X, int ld, int Cin,
                               float* __restrict__ xx) {
    int pt = blockIdx.x * blockDim.x + threadIdx.x;
    if (pt < NPTS_TOT) {
        const float* r = X + (size_t)pt * ld;
        float s = 0.f;
        for (int c = 0; c < Cin; c++) {
            float v = r[c];
            s = __fadd_rn(s, __fmul_rn(v, v));
        }
        xx[pt] = s;
    }
}

// L4 combined weights: WC[o] = W1[o]; WC[Cout+o] = W2[o]-W1[o]
__global__ void wcomb_kernel(const float* __restrict__ W, int Cin, int Cout,
                             float* __restrict__ WC) {
    int i = blockIdx.x * blockDim.x + threadIdx.x;
    if (i < 2*Cout*Cin) {
        int o = i / Cin, c = i % Cin;
        if (o < Cout) WC[i] = W[(size_t)o*(2*Cin) + c];
        else {
            int oo = o - Cout;
            WC[i] = __fsub_rn(W[(size_t)oo*(2*Cin) + Cin + c],
                              W[(size_t)oo*(2*Cin) + c]);
        }
    }
}

// From fp64 sums: m, rs — then RE-ZEROES the stats slots for the next phase.
__global__ void bnfin_kernel(double* __restrict__ sum, double* __restrict__ sqs,
                             double cnt, int C,
                             float* __restrict__ M, float* __restrict__ RS) {
    int o = blockIdx.x * blockDim.x + threadIdx.x;
    if (o < C) {
        double mu = sum[o] / cnt;
        float m = (float)mu;
        double vd = sqs[o]/cnt - 2.0*(double)m*mu + (double)m*(double)m;
        float v = (float)vd;
        M[o]  = m;
        RS[o] = rsqrtf(__fadd_rn(v, EPSB));
        sum[o] = 0.0;
        sqs[o] = 0.0;
    }
}

// ------------------------- TF32x3 tensor-core GEMM (value path only) -------
// C[b,i,j] = sum_c X[b,i,c]*W[j,c] via mma.sync.m16n8k8 tf32, operands split
// hi/lo (3 mmas, lo*lo dropped): per-product error ~2^-23 ≈ fp32.
// Used ONLY for conv5 / L4-PQ (no kNN downstream; 1e-3 value tolerance).
__device__ __forceinline__ void tf32split(float x, uint32_t& hi, uint32_t& lo) {
    uint32_t h; asm("cvt.rna.tf32.f32 %0, %1;" : "=r"(h) : "f"(x));
    float hf = __uint_as_float(h);
    float lf = __fsub_rn(x, hf);
    uint32_t l; asm("cvt.rna.tf32.f32 %0, %1;" : "=r"(l) : "f"(lf));
    hi = h; lo = l;
}

__device__ __forceinline__ void mma_tf32(float* c, const uint32_t* a, const uint32_t* b) {
    asm volatile(
        "mma.sync.aligned.m16n8k8.row.col.f32.tf32.tf32.f32 "
        "{%0,%1,%2,%3}, {%4,%5,%6,%7}, {%8,%9}, {%0,%1,%2,%3};"
        : "+f"(c[0]), "+f"(c[1]), "+f"(c[2]), "+f"(c[3])
        : "r"(a[0]), "r"(a[1]), "r"(a[2]), "r"(a[3]), "r"(b[0]), "r"(b[1]));
}

__global__ void __launch_bounds__(256)
gemm_tc_kernel(const float* __restrict__ X, int ldx, int Cin,
               const float* __restrict__ W,
               float* __restrict__ out, int ldo) {
    int b  = blockIdx.z;
    int i0 = blockIdx.x * 128;
    int j0 = blockIdx.y * 64;
    __shared__ float As[2][16][132];
    __shared__ float Bs[2][16][68];
    int tid = threadIdx.x;
    int warp = tid >> 5, lane = tid & 31;
    int wm = warp >> 1, wn = warp & 1;          // warp tile: 32 rows x 32 cols
    int t4 = lane & 3, g8 = lane >> 2;
    float c[2][4][4] = {};
    const float* Xb = X + (size_t)b * NPT * ldx;
    int T = (Cin + 15) >> 4;
    #pragma unroll
    for (int n = 0; n < 8; n++) {
        int l = tid + 256*n; int r = l >> 4, cc = l & 15;
        As[0][cc][r] = (cc < Cin) ? Xb[(size_t)(i0 + r)*ldx + cc] : 0.f;
    }
    #pragma unroll
    for (int n = 0; n < 4; n++) {
        int l = tid + 256*n; int r = l >> 4, cc = l & 15;
        Bs[0][cc][r] = (cc < Cin) ? W[(size_t)(j0 + r)*Cin + cc] : 0.f;
    }
    __syncthreads();
    for (int t = 0; t < T; t++) {
        int cur = t & 1, nxt = cur ^ 1;
        float pa[8], pb[4];
        if (t + 1 < T) {
            int k0n = (t + 1) << 4;
            #pragma unroll
            for (int n = 0; n < 8; n++) {
                int l = tid + 256*n; int r = l >> 4, cc = l & 15; int kk = k0n + cc;
                pa[n] = (kk < Cin) ? Xb[(size_t)(i0 + r)*ldx + kk] : 0.f;
            }
            #pragma unroll
            for (int n = 0; n < 4; n++) {
                int l = tid + 256*n; int r = l >> 4, cc = l & 15; int kk = k0n + cc;
                pb[n] = (kk < Cin) ? W[(size_t)(j0 + r)*Cin + kk] : 0.f;
            }
        }
        #pragma unroll
        for (int k8 = 0; k8 < 16; k8 += 8) {
            uint32_t ah[2][4], al[2][4], bh[4][2], bl[4][2];
            #pragma unroll
            for (int ms = 0; ms < 2; ms++) {
                int rb = wm*32 + ms*16 + g8;
                tf32split(As[cur][k8 + t4    ][rb    ], ah[ms][0], al[ms][0]);
                tf32split(As[cur][k8 + t4    ][rb + 8], ah[ms][1], al[ms][1]);
                tf32split(As[cur][k8 + t4 + 4][rb    ], ah[ms][2], al[ms][2]);
                tf32split(As[cur][k8 + t4 + 4][rb + 8], ah[ms][3], al[ms][3]);
            }
            #pragma unroll
            for (int ns = 0; ns < 4; ns++) {
                int cb = wn*32 + ns*8 + g8;
                tf32split(Bs[cur][k8 + t4    ][cb], bh[ns][0], bl[ns][0]);
                tf32split(Bs[cur][k8 + t4 + 4][cb], bh[ns][1], bl[ns][1]);
            }
            #pragma unroll
            for (int ms = 0; ms < 2; ms++)
                #pragma unroll
                for (int ns = 0; ns < 4; ns++) {
                    mma_tf32(c[ms][ns], ah[ms], bh[ns]);
                    mma_tf32(c[ms][ns], al[ms], bh[ns]);
                    mma_tf32(c[ms][ns], ah[ms], bl[ns]);
                }
        }
        if (t + 1 < T) {
            #pragma unroll
            for (int n = 0; n < 8; n++) {
                int l = tid + 256*n; int r = l >> 4, cc = l & 15;
                As[nxt][cc][r] = pa[n];
            }
            #pragma unroll
            for (int n = 0; n < 4; n++) {
                int l = tid + 256*n; int r = l >> 4, cc = l & 15;
                Bs[nxt][cc][r] = pb[n];
            }
        }
        __syncthreads();
    }
    float* outb = out + (size_t)b * NPT * ldo;
    #pragma unroll
    for (int ms = 0; ms < 2; ms++)
        #pragma unroll
        for (int ns = 0; ns < 4; ns++) {
            int r0 = i0 + wm*32 + ms*16 + g8;
            int cc = j0 + wn*32 + ns*8 + t4*2;
            *(float2*)&outb[(size_t)r0*ldo + cc]
                = make_float2(c[ms][ns][0], c[ms][ns][1]);
            *(float2*)&outb[(size_t)(r0 + 8)*ldo + cc]
                = make_float2(c[ms][ns][2], c[ms][ns][3]);
        }
}

// pd[b,i,j] = (-xx[j] - (-2*dot_ij)) - xx[i], dot via ascending fma (exact fp32)
// R10 configuration: 128x64 tile, 8x4 micro, double-buffered.
__global__ void gram_kernel(const float* __restrict__ X, int ldx, int Cin,
                            const float* __restrict__ xx, float* __restrict__ S) {
    int b  = blockIdx.z;
    int i0 = blockIdx.x * 128;
    int j0 = blockIdx.y * 64;
    __shared__ float As[2][16][132];
    __shared__ float Bs[2][16][68];
    int tid = threadIdx.x, tx = tid % 16, ty = tid / 16;
    float acc[8][4] = {};
    const float* Xb = X + (size_t)b * NPT * ldx;
    int T = (Cin + 15) >> 4;
    #pragma unroll
    for (int n = 0; n < 8; n++) {
        int l = tid + 256*n; int r = l >> 4, c = l & 15;
        As[0][c][r] = (c < Cin) ? Xb[(size_t)(i0 + r)*ldx + c] : 0.f;
    }
    #pragma unroll
    for (int n = 0; n < 4; n++) {
        int l = tid + 256*n; int r = l >> 4, c = l & 15;
        Bs[0][c][r] = (c < Cin) ? Xb[(size_t)(j0 + r)*ldx + c] : 0.f;
    }
    __syncthreads();
    for (int t = 0; t < T; t++) {
        int cur = t & 1, nxt = cur ^ 1;
        float pa[8], pb[4];
        if (t + 1 < T) {
            int k0n = (t + 1) << 4;
            #pragma unroll
            for (int n = 0; n < 8; n++) {
                int l = tid + 256*n; int r = l >> 4, c = l & 15; int kk = k0n + c;
                pa[n] = (kk < Cin) ? Xb[(size_t)(i0 + r)*ldx + kk] : 0.f;
            }
            #pragma unroll
            for (int n = 0; n < 4; n++) {
                int l = tid + 256*n; int r = l >> 4, c = l & 15; int kk = k0n + c;
                pb[n] = (kk < Cin) ? Xb[(size_t)(j0 + r)*ldx + kk] : 0.f;
            }
        }
        #pragma unroll
        for (int kk = 0; kk < 16; kk++) {
            float4 a0 = *(const float4*)&As[cur][kk][ty*8];
            float4 a1 = *(const float4*)&As[cur][kk][ty*8 + 4];
            float4 bq = *(const float4*)&Bs[cur][kk][tx*4];
            float a[8]  = {a0.x,a0.y,a0.z,a0.w,a1.x,a1.y,a1.z,a1.w};
            float bv[4] = {bq.x, bq.y, bq.z, bq.w};
            #pragma unroll
            for (int i = 0; i < 8; i++)
                #pragma unroll
                for (int j = 0; j < 4; j++)
                    acc[i][j] = __fmaf_rn(a[i], bv[j], acc[i][j]);
        }
        if (t + 1 < T) {
            #pragma unroll
            for (int n = 0; n < 8; n++) {
                int l = tid + 256*n; int r = l >> 4, c = l & 15;
                As[nxt][c][r] = pa[n];
            }
            #pragma unroll
            for (int n = 0; n < 4; n++) {
                int l = tid + 256*n; int r = l >> 4, c = l & 15;
                Bs[nxt][c][r] = pb[n];
            }
        }
        __syncthreads();
    }
    float* Sb = S + (size_t)b * NPT * NPT;
    const float* xxb = xx + (size_t)b * NPT;
    float4 xjq = *(const float4*)&xxb[j0 + tx*4];
    float xjv[4] = {xjq.x, xjq.y, xjq.z, xjq.w};
    #pragma unroll
    for (int i = 0; i < 8; i++) {
        float xi = xxb[i0 + ty*8 + i];
        float e[4];
        #pragma unroll
        for (int j = 0; j < 4; j++) {
            float inner = __fmul_rn(-2.f, acc[i][j]);
            float t1 = __fsub_rn(-xjv[j], inner);
            e[j] = __fsub_rn(t1, xi);
        }
        *(float4*)&Sb[(size_t)(i0 + ty*8 + i)*NPT + (j0 + tx*4)]
            = make_float4(e[0], e[1], e[2], e[3]);
    }
}

// ------------------------- top-k (warp per row, register-resident) ----------
// jax.lax.top_k semantics: values descending, ties broken by lowest index.
// Lane argmax via group-of-4 + tree-of-8 (prefer lower index on ties).
__global__ void topk_kernel(const float* __restrict__ S, int* __restrict__ idxout) {
    int gwarp = (blockIdx.x * blockDim.x + threadIdx.x) >> 5;
    int lane  = threadIdx.x & 31;
    if (gwarp >= NPTS_TOT) return;
    const float* row = S + (size_t)gwarp * NPT;

    float v[32];
    #pragma unroll
    for (int j = 0; j < 32; j++) v[j] = row[lane + (j << 5)];

    int* outp = idxout + (size_t)gwarp * KNN;
    for (int k = 0; k < KNN; k++) {
        float gv[8]; int gj[8];
        #pragma unroll
        for (int g = 0; g < 8; g++) {
            float bv_ = v[4*g]; int bj_ = 4*g;
            #pragma unroll
            for (int e = 1; e < 4; e++)
                if (v[4*g + e] > bv_) { bv_ = v[4*g + e]; bj_ = 4*g + e; }
            gv[g] = bv_; gj[g] = bj_;
        }
        #pragma unroll
        for (int st = 1; st < 8; st <<= 1)
            #pragma unroll
            for (int g = 0; g < 8; g += 2*st)
                if (gv[g + st] > gv[g]) { gv[g] = gv[g + st]; gj[g] = gj[g + st]; }
        float wv = gv[0];
        int   wm = lane + (gj[0] << 5);
        #pragma unroll
        for (int off = 16; off > 0; off >>= 1) {
            float ov = __shfl_xor_sync(0xffffffff, wv, off);
            int   om = __shfl_xor_sync(0xffffffff, wm, off);
            if (ov > wv || (ov == wv && om < wm)) { wv = ov; wm = om; }
        }
        if (lane == 0) outp[k] = wm;
        if ((wm & 31) == lane) {
            int jj = wm >> 5;
            #pragma unroll
            for (int j = 0; j < 32; j++)
                if (j == jj) v[j] = -FLTMAX;
        }
    }
}

// ------------------------- per-edge EXACT fp32 EdgeConv (L1-L3, R10) --------
__global__ void edgeconv_kernel(const float* __restrict__ X, int ld, int Cin, int Cout,
                                const float* __restrict__ W,
                                const int* __restrict__ idx,
                                float* __restrict__ ymax, float* __restrict__ ymin,
                                double* __restrict__ chanSum, double* __restrict__ chanSqs) {
    __shared__ float  As[16][81];
    __shared__ float  Bs[16][68];
    __shared__ double wsum[4][64], wsq[4][64];
    __shared__ int sidx[80];
    int tid = threadIdx.x;
    int pt0 = blockIdx.x * 4;
    int o0  = blockIdx.y * 64;
    int brow = (pt0 / NPT) * NPT;
    if (tid < 80) sidx[tid] = idx[(size_t)(pt0 + tid/20)*KNN + tid%20];
    __syncthreads();
    int eg = tid >> 3;          // 0..15 (5 edges each; warp w holds eg 4w..4w+3 = point w)
    int og = tid & 7;           // 0..7  (8 outs each)
    int warp = tid >> 5, lane = tid & 31;
    float acc[5][8] = {};
    int C2 = 2*Cin;
    for (int k0 = 0; k0 < C2; k0 += 16) {
        for (int l = tid; l < 64*16; l += 128) {
            int r = l >> 4, c = l & 15;
            int cc = k0 + c;
            Bs[c][r] = (cc < C2) ? W[(size_t)(o0 + r)*C2 + cc] : 0.f;
        }
        for (int l = tid; l < 80*16; l += 128) {
            int r = l >> 4, c = l & 15;
            int cc = k0 + c;
            int p = r / 20;
            float v = 0.f;
            if (cc < Cin) {
                int m = sidx[r];
                v = __fsub_rn(X[(size_t)(brow + m)*ld + cc], X[(size_t)(pt0 + p)*ld + cc]);
            } else if (cc < C2) {
                v = X[(size_t)(pt0 + p)*ld + (cc - Cin)];
            }
            As[c][r] = v;
        }
        __syncthreads();
        #pragma unroll
        for (int kk = 0; kk < 16; kk++) {
            float a[5];
            #pragma unroll
            for (int i = 0; i < 5; i++) a[i] = As[kk][eg*5 + i];
            float4 b0 = *(const float4*)&Bs[kk][og*8];
            float4 b1 = *(const float4*)&Bs[kk][og*8 + 4];
            float bv[8] = {b0.x,b0.y,b0.z,b0.w,b1.x,b1.y,b1.z,b1.w};
            #pragma unroll
            for (int i = 0; i < 5; i++)
                #pragma unroll
                for (int j = 0; j < 8; j++)
                    acc[i][j] = __fmaf_rn(a[i], bv[j], acc[i][j]);
        }
        __syncthreads();
    }
    #pragma unroll
    for (int j = 0; j < 8; j++) {
        float y0 = acc[0][j];
        float mx = y0, mn = y0;
        double s = (double)y0, q = (double)y0*(double)y0;
        #pragma unroll
        for (int i = 1; i < 5; i++) {
            float y = acc[i][j];
            mx = fmaxf(mx, y); mn = fminf(mn, y);
            s += (double)y; q += (double)y*(double)y;
        }
        mx = fmaxf(mx, __shfl_xor_sync(0xffffffff, mx, 8));
        mx = fmaxf(mx, __shfl_xor_sync(0xffffffff, mx, 16));
        mn = fminf(mn, __shfl_xor_sync(0xffffffff, mn, 8));
        mn = fminf(mn, __shfl_xor_sync(0xffffffff, mn, 16));
        s += __shfl_xor_sync(0xffffffff, s, 8);
        s += __shfl_xor_sync(0xffffffff, s, 16);
        q += __shfl_xor_sync(0xffffffff, q, 8);
        q += __shfl_xor_sync(0xffffffff, q, 16);
        if (lane < 8) {
            int oj = lane*8 + j;
            ymax[(size_t)(pt0 + warp)*Cout + o0 + oj] = mx;
            ymin[(size_t)(pt0 + warp)*Cout + o0 + oj] = mn;
            wsum[warp][oj] = s;
            wsq [warp][oj] = q;
        }
    }
    __syncthreads();
    if (tid < 64) {
        double S = wsum[0][tid] + wsum[1][tid] + wsum[2][tid] + wsum[3][tid];
        double Q = wsq [0][tid] + wsq [1][tid] + wsq [2][tid] + wsq [3][tid];
        atomicAdd(&chanSum[o0 + tid], S);
        atomicAdd(&chanSqs[o0 + tid], Q);
    }
}

// ------------------------- L4 factorized gather -----------------------------
#define PPB 16
__global__ void gather_kernel(const float* __restrict__ PQ,
                              const int* __restrict__ idx,
                              float* __restrict__ ymax, float* __restrict__ ymin,
                              double* __restrict__ chanSum, double* __restrict__ chanSqs) {
    int o = threadIdx.x;                 // 256 = Cout
    int base = blockIdx.x * PPB;
    __shared__ int sidx[PPB][KNN];
    for (int l = o; l < PPB*KNN; l += 256)
        sidx[l/KNN][l%KNN] = idx[(size_t)(base + l/KNN)*KNN + l%KNN];
    __syncthreads();
    double s = 0.0, q = 0.0;
    for (int p = 0; p < PPB; p++) {
        int pt = base + p;
        int brow = (pt >> 10) << 10;
        float Qv = PQ[(size_t)pt*512 + 256 + o];
        float mx = -FLTMAX, mn = FLTMAX;
        #pragma unroll
        for (int k = 0; k < KNN; k++) {
            float y = __fadd_rn(PQ[(size_t)(brow + sidx[p][k])*512 + o], Qv);
            mx = fmaxf(mx, y); mn = fminf(mn, y);
            double yd = (double)y;
            s += yd; q += yd*yd;
        }
        ymax[(size_t)pt*256 + o] = mx;
        ymin[(size_t)pt*256 + o] = mn;
    }
    atomicAdd(&chanSum[o], s);
    atomicAdd(&chanSqs[o], q);
}

// out = lrelu(((v - m)*rs)*w + b), v = ymax if w>=0 else ymin — exact ref op order
__global__ void apply_edge_kernel(const float* __restrict__ ymax,
                                  const float* __restrict__ ymin,
                                  const float* __restrict__ M,
                                  const float* __restrict__ RS,
                                  const float* __restrict__ bw,
                                  const float* __restrict__ bb,
                                  int Cout, float* __restrict__ out, int ldo) {
    int o  = threadIdx.x;
    int pt = blockIdx.x;
    float w = bw[o];
    float v = (w >= 0.f) ? ymax[(size_t)pt*Cout + o] : ymin[(size_t)pt*Cout + o];
    float t = __fsub_rn(v, M[o]);
    t = __fmul_rn(t, RS[o]);
    t = __fmul_rn(t, w);
    t = __fadd_rn(t, bb[o]);
    out[(size_t)pt*ldo + o] = (t >= 0.f) ? t : __fmul_rn(NEG, t);
}

// ------------------------- conv5 stats + pooled reduce ----------------------
__global__ void y5stats_kernel(const float* __restrict__ Y5,
                               double* __restrict__ chanSum, double* __restrict__ chanSqs) {
    int cg = blockIdx.x * 64;
    int rg = blockIdx.y * 256;
    int t = threadIdx.x; int c = t % 64, ph = t / 64;
    double s = 0.0, sq = 0.0;
    for (int r = ph; r < 256; r += 4) {
        double v = (double)Y5[(size_t)(rg + r)*1024 + cg + c];
        s += v; sq += v*v;
    }
    __shared__ double ss[256], qq[256];
    ss[t] = s; qq[t] = sq; __syncthreads();
    if (ph == 0) {
        s  = ss[c] + ss[c+64] + ss[c+128] + ss[c+192];
        sq = qq[c] + qq[c+64] + qq[c+128] + qq[c+192];
        atomicAdd(&chanSum[cg+c], s);
        atomicAdd(&chanSqs[cg+c], sq);
    }
}

__global__ void y5reduce_kernel(const float* __restrict__ Y5,
                                const float* __restrict__ M, const float* __restrict__ RS,
                                const float* __restrict__ bw, const float* __restrict__ bb,
                                float* __restrict__ feat) {
    int cg = blockIdx.x * 64; int b = blockIdx.y;
    int t = threadIdx.x; int c = t % 64, ph = t / 64;
    float m = M[cg+c], rs = RS[cg+c], w = bw[cg+c], bbv = bb[cg+c];
    float mx = -FLTMAX, s = 0.f;
    for (int n = ph; n < NPT; n += 4) {
        float v = Y5[((size_t)b*NPT + n)*1024 + cg + c];
        float tv = __fsub_rn(v, m);
        tv = __fmul_rn(tv, rs);
        tv = __fmul_rn(tv, w);
        tv = __fadd_rn(tv, bbv);
        tv = (tv >= 0.f) ? tv : __fmul_rn(NEG, tv);
        mx = fmaxf(mx, tv); s += tv;
    }
    __shared__ float sm[256], ssum[256];
    sm[t] = mx; ssum[t] = s; __syncthreads();
    if (ph == 0) {
        mx = fmaxf(fmaxf(sm[c], sm[c+64]), fmaxf(sm[c+128], sm[c+192]));
        s  = ssum[c] + ssum[c+64] + ssum[c+128] + ssum[c+192];
        feat[(size_t)b*2048 + cg + c]        = mx;
        feat[(size_t)b*2048 + 1024 + cg + c] = __fdiv_rn(s, 1024.f);
    }
}

// ------------------------- head: linear + BN(batch=8) + lrelu ---------------
__global__ void head_kernel(const float* __restrict__ in, int Cin,
                            const float* __restrict__ W, const float* __restrict__ bias,
                            const float* __restrict__ bw, const float* __restrict__ bb,
                            float* __restrict__ out, int Cout) {
    int o = blockIdx.x;
    int t = threadIdx.x;
    float acc[8] = {0,0,0,0,0,0,0,0};
    for (int c = t; c < Cin; c += 256) {
        float w = W[(size_t)o*Cin + c];
        #pragma unroll
        for (int b = 0; b < 8; b++) acc[b] = __fmaf_rn(w, in[(size_t)b*Cin + c], acc[b]);
    }
    #pragma unroll
    for (int b = 0; b < 8; b++)
        #pragma unroll
        for (int off = 16; off > 0; off >>= 1)
            acc[b] += __shfl_xor_sync(0xffffffff, acc[b], off);
    __shared__ float ws[8][8];
    int warp = t >> 5, lane = t & 31;
    if (lane == 0)
        #pragma unroll
        for (int b = 0; b < 8; b++) ws[warp][b] = acc[b];
    __syncthreads();
    if (t == 0) {
        float z[8];
        #pragma unroll
        for (int b = 0; b < 8; b++) {
            float s = bias[o];
            #pragma unroll
            for (int w = 0; w < 8; w++) s += ws[w][b];
            z[b] = s;
        }
        float m = 0.f;
        #pragma unroll
        for (int b = 0; b < 8; b++) m += z[b];
        m *= 0.125f;
        float v = 0.f;
        #pragma unroll
        for (int b = 0; b < 8; b++) { float d = __fsub_rn(z[b], m); v = __fmaf_rn(d, d, v); }
        v *= 0.125f;
        float rs = rsqrtf(__fadd_rn(v, EPSB));
        #pragma unroll
        for (int b = 0; b < 8; b++) {
            float tt = __fsub_rn(z[b], m);
            tt = __fmul_rn(tt, rs);
            tt = __fmul_rn(tt, bw[o]);
            tt = __fadd_rn(tt, bb[o]);
            out[(size_t)b*Cout + o] = (tt >= 0.f) ? tt : __fmul_rn(NEG, tt);
        }
    }
}

__global__ void final_kernel(const float* __restrict__ H2, const float* __restrict__ W,
                             const float* __restrict__ bias, float* __restrict__ out) {
    int i = blockIdx.x * blockDim.x + threadIdx.x;
    if (i < 8*40) {
        int b = i / 40, o = i % 40;
        float s = bias[o];
        for (int c = 0; c < 256; c++)
            s = __fmaf_rn(H2[(size_t)b*256 + c], W[(size_t)o*256 + c], s);
        out[i] = s;
    }
}

// ------------------------- host driver --------------------------------------
extern "C" void kernel_launch(void* const* d_in, const int* in_sizes, int n_in,
                              void* d_out, int out_size) {
    const float* x   = (const float*)d_in[0];
    const float* c1w = (const float*)d_in[1];
    const float* c2w = (const float*)d_in[2];
    const float* c3w = (const float*)d_in[3];
    const float* c4w = (const float*)d_in[4];
    const float* c5w = (const float*)d_in[5];
    const float* bnw_[5] = { (const float*)d_in[6], (const float*)d_in[8],
                             (const float*)d_in[10], (const float*)d_in[12],
                             (const float*)d_in[14] };
    const float* bnb_[5] = { (const float*)d_in[7], (const float*)d_in[9],
                             (const float*)d_in[11], (const float*)d_in[13],
                             (const float*)d_in[15] };
    const float* b6w = (const float*)d_in[16];
    const float* b6b = (const float*)d_in[17];
    const float* b7w = (const float*)d_in[18];
    const float* b7b = (const float*)d_in[19];
    const float* l1w = (const float*)d_in[20];
    const float* l1b = (const float*)d_in[21];
    const float* l2w = (const float*)d_in[22];
    const float* l2b = (const float*)d_in[23];
    const float* l3w = (const float*)d_in[24];
    const float* l3b = (const float*)d_in[25];

    float *X0,*XX,*PD,*YMX,*YMN,*CAT,*Y5,*WC,*PQ,*M,*RS,*FEAT,*H1,*H2;
    double *SUM,*SQS;
    int *IDX;
    cudaGetSymbolAddress((void**)&X0,  g_X0);
    cudaGetSymbolAddress((void**)&XX,  g_XX);
    cudaGetSymbolAddress((void**)&PD,  g_PD);
    cudaGetSymbolAddress((void**)&IDX, g_IDX);
    cudaGetSymbolAddress((void**)&YMX, g_YMX);
    cudaGetSymbolAddress((void**)&YMN, g_YMN);
    cudaGetSymbolAddress((void**)&CAT, g_CAT);
    cudaGetSymbolAddress((void**)&Y5,  g_Y5);
    cudaGetSymbolAddress((void**)&WC,  g_WC);
    cudaGetSymbolAddress((void**)&PQ,  g_PQ);
    cudaGetSymbolAddress((void**)&SUM, g_SUM);
    cudaGetSymbolAddress((void**)&SQS, g_SQS);
    cudaGetSymbolAddress((void**)&M,   g_M);
    cudaGetSymbolAddress((void**)&RS,  g_RS);
    cudaGetSymbolAddress((void**)&FEAT,g_FEAT);
    cudaGetSymbolAddress((void**)&H1,  g_H1);
    cudaGetSymbolAddress((void**)&H2,  g_H2);

    transpose_x_kernel<<<(BSZ*NPT*3 + 255)/256, 256>>>(x, X0);

    const float* convW[4] = { c1w, c2w, c3w, c4w };
    int Cin [4] = { 3, 64, 64, 128 };
    int Cout[4] = { 64, 64, 128, 256 };
    int outOff[4] = { 0, 64, 128, 256 };

    for (int L = 0; L < 4; L++) {
        const float* Xin = (L == 0) ? X0 : (CAT + outOff[L-1]);
        int ldin = (L == 0) ? 3 : 512;
        int Ci = Cin[L], Co = Cout[L];

        rownorm_kernel<<<(NPTS_TOT + 255)/256, 256>>>(Xin, ldin, Ci, XX);
        dim3 ggrid(NPT/128, NPT/64, BSZ);
        gram_kernel<<<ggrid, 256>>>(Xin, ldin, Ci, XX, PD);
        topk_kernel<<<(NPTS_TOT*32)/256, 256>>>(PD, IDX);

        if (L < 3) {
            // exact per-edge path: output feeds the next layer's kNN
            dim3 egrid(NPTS_TOT/4, Co/64);
            edgeconv_kernel<<<egrid, 128>>>(Xin, ldin, Ci, Co, convW[L], IDX,
                                            YMX, YMN, SUM, SQS);
        } else {
            // L4 factorized path: no kNN downstream, value-tolerance only
            wcomb_kernel<<<(2*Co*Ci + 255)/256, 256>>>(convW[L], Ci, Co, WC);
            dim3 pqgrid(NPT/128, (2*Co)/64, BSZ);
            gemm_tc_kernel<<<pqgrid, 256>>>(Xin, ldin, Ci, WC, PQ, 2*Co);
            gather_kernel<<<NPTS_TOT/PPB, 256>>>(PQ, IDX, YMX, YMN, SUM, SQS);
        }

        bnfin_kernel<<<(Co + 255)/256, 256>>>(SUM, SQS,
                                              (double)(BSZ*NPT*KNN), Co, M, RS);
        apply_edge_kernel<<<NPTS_TOT, Co>>>(YMX, YMN, M, RS, bnw_[L], bnb_[L],
                                            Co, CAT + outOff[L], 512);
    }

    // conv5: Y5[b,n,o] = CAT[b,n,:] @ c5w[o,:]   (TF32x3 tensor cores)
    dim3 g5(NPT/128, 1024/64, BSZ);
    gemm_tc_kernel<<<g5, 256>>>(CAT, 512, 512, c5w, Y5, 1024);
    dim3 sgrid(16, 32);
    y5stats_kernel<<<sgrid, 256>>>(Y5, SUM, SQS);
    bnfin_kernel<<<4, 256>>>(SUM, SQS, (double)(BSZ*NPT), 1024, M, RS);
    dim3 rgrid(16, BSZ);
    y5reduce_kernel<<<rgrid, 256>>>(Y5, M, RS, bnw_[4], bnb_[4], FEAT);

    head_kernel<<<512, 256>>>(FEAT, 2048, l1w, l1b, b6w, b6b, H1, 512);
    head_kernel<<<256, 256>>>(H1,   512,  l2w, l2b, b7w, b7b, H2, 256);
    final_kernel<<<2, 256>>>(H2, l3w, l3b, (float*)d_out);
}